// round 2
// baseline (speedup 1.0000x reference)
#include <cuda_runtime.h>
#include <cstdint>

#define DL 21
#define SS 512
#define HW (SS*SS)
#define NB 4
#define NELEM (NB*DL*HW)   // 22,020,096 elements (~84 MB fp32)

// Scratch buffers for three of the four directional results (4th goes to d_out).
__device__ __align__(16) float g_tA[NELEM];   // L_LR - 3u
__device__ __align__(16) float g_tB[NELEM];   // L_RL
__device__ __align__(16) float g_tC[NELEM];   // L_TD

// One DP step: returns min_k ( shfl(L,k) + w * Vc[k] ).
// Three parallel min-accumulator chains to cut dependency depth.
__device__ __forceinline__ float mp_min(float L, float wval, const float (&Vc)[DL]) {
    const unsigned FM = 0xffffffffu;
    float m0 = fmaf(wval, Vc[0], __shfl_sync(FM, L, 0));
    float m1 = fmaf(wval, Vc[1], __shfl_sync(FM, L, 1));
    float m2 = fmaf(wval, Vc[2], __shfl_sync(FM, L, 2));
#pragma unroll
    for (int k = 3; k < DL; k += 3) {
        m0 = fminf(m0, fmaf(wval, Vc[k    ], __shfl_sync(FM, L, k    )));
        m1 = fminf(m1, fmaf(wval, Vc[k + 1], __shfl_sync(FM, L, k + 1)));
        m2 = fminf(m2, fmaf(wval, Vc[k + 2], __shfl_sync(FM, L, k + 2)));
    }
    return fminf(m0, fminf(m1, m2));
}

// Horizontal sweep (scan along w). up/wp/op point at the row start.
template<bool REV, bool SUB3U>
__device__ __forceinline__ void sweep_h(const float* __restrict__ up,
                                        const float* __restrict__ wp,
                                        float* __restrict__ op,
                                        const float (&Vc)[DL], bool active) {
    float L = 0.0f;
#pragma unroll 1
    for (int c = 0; c < SS / 4; c++) {
        const int base = REV ? (SS - 4 - 4 * c) : 4 * c;
        float4 u4 = *reinterpret_cast<const float4*>(up + base);
        float4 w4 = *reinterpret_cast<const float4*>(wp + base);
        float uu[4] = {u4.x, u4.y, u4.z, u4.w};
        float ww[4] = {w4.x, w4.y, w4.z, w4.w};
        float rr[4];
#pragma unroll
        for (int j = 0; j < 4; j++) {
            const int jj = REV ? 3 - j : j;
            float uval = uu[jj];
            if (j == 0 && c == 0) {
                L = uval;                      // border: L = u
            } else {
                L = uval + mp_min(L, ww[jj], Vc);
            }
            rr[jj] = SUB3U ? (L - 3.0f * uval) : L;
        }
        if (active)
            *reinterpret_cast<float4*>(op + base) = make_float4(rr[0], rr[1], rr[2], rr[3]);
    }
}

// Vertical sweep (scan along h, stride SS). up/wp/op point at the column start.
template<bool REV>
__device__ __forceinline__ void sweep_v(const float* __restrict__ up,
                                        const float* __restrict__ wp,
                                        float* __restrict__ op,
                                        const float (&Vc)[DL], bool active) {
    float L;
    {
        const int pos = REV ? (SS - 1) : 0;
        float uval = __ldg(up + (size_t)pos * SS);
        L = uval;
        if (active) op[(size_t)pos * SS] = L;
    }
#pragma unroll 4
    for (int t = 1; t < SS; t++) {
        const int pos = REV ? (SS - 1 - t) : t;
        float uval = __ldg(up + (size_t)pos * SS);
        float wval = __ldg(wp + (size_t)pos * SS);
        L = uval + mp_min(L, wval, Vc);
        if (active) op[(size_t)pos * SS] = L;
    }
}

// One kernel, all 4 directions: 8192 warps, each owns one (dir, b, line) chain.
__global__ void __launch_bounds__(256)
sweep_all(const float* __restrict__ unary,
          const float* __restrict__ ew,
          const float* __restrict__ lc,
          float* __restrict__ dout) {
    const int gw   = (blockIdx.x * blockDim.x + threadIdx.x) >> 5;
    const int lane = threadIdx.x & 31;
    const int dir  = gw >> 11;        // 2048 chains per direction
    const int r    = gw & 2047;
    const int b    = r >> 9;
    const int line = r & 511;
    const int l    = (lane < DL) ? lane : 0;
    const bool active = (lane < DL);

    // Per-lane column of the label-context matrix: Vc[k] = V[k][l]
    float Vc[DL];
#pragma unroll
    for (int k = 0; k < DL; k++) Vc[k] = __ldg(lc + k * DL + l);

    const size_t plane = (size_t)(b * DL + l) * HW;
    const float* wp = ew + (size_t)(b * 4 + dir) * HW;
    const float* up = unary + plane;

    if (dir == 0) {            // left -> right
        const size_t off = (size_t)line * SS;
        sweep_h<false, true >(up + off, wp + off, g_tA + plane + off, Vc, active);
    } else if (dir == 1) {     // right -> left
        const size_t off = (size_t)line * SS;
        sweep_h<true,  false>(up + off, wp + off, g_tB + plane + off, Vc, active);
    } else if (dir == 2) {     // top -> down
        sweep_v<false>(up + line, wp + line, g_tC + plane + line, Vc, active);
    } else {                   // bottom -> up
        sweep_v<true >(up + line, wp + line, dout + plane + line, Vc, active);
    }
}

// out = L_BU(already in out) + (L_LR - 3u) + L_RL + L_TD
__global__ void __launch_bounds__(256)
combine(float* __restrict__ dout) {
    const int i = blockIdx.x * blockDim.x + threadIdx.x;
    if (i >= NELEM / 4) return;
    float4* o = reinterpret_cast<float4*>(dout);
    const float4* pa = reinterpret_cast<const float4*>(g_tA);
    const float4* pb = reinterpret_cast<const float4*>(g_tB);
    const float4* pc = reinterpret_cast<const float4*>(g_tC);
    float4 x = o[i], a = pa[i], bq = pb[i], c = pc[i];
    x.x += a.x + bq.x + c.x;
    x.y += a.y + bq.y + c.y;
    x.z += a.z + bq.z + c.z;
    x.w += a.w + bq.w + c.w;
    o[i] = x;
}

extern "C" void kernel_launch(void* const* d_in, const int* in_sizes, int n_in,
                              void* d_out, int out_size) {
    const float* unary = (const float*)d_in[0];   // (4,1,21,512,512)
    const float* ew    = (const float*)d_in[1];   // (4,4,512,512)
    const float* lc    = (const float*)d_in[2];   // (21,21)
    float* out = (float*)d_out;                   // (4,1,21,512,512)

    // 8192 chains (4 dirs x 4 batches x 512 lines), 1 warp each, 8 warps/block
    sweep_all<<<1024, 256>>>(unary, ew, lc, out);
    combine<<<(NELEM / 4 + 255) / 256, 256>>>(out);
}

// round 3
// speedup vs baseline: 1.3714x; 1.3714x over previous
#include <cuda_runtime.h>
#include <cstdint>

#define DL 21
#define SS 512
#define HW (SS*SS)
#define NB 4
#define NP (NB*HW)          // 1,048,576 positions
#define NE (NP*DL)          // 22,020,096 elements (~84 MB fp32)
#define TP 128              // positions per transpose tile

// Label-innermost copy of unary: ut[b][p][l]
__device__ __align__(16) float g_ut[NE];
// Directional results, (b, p, l) layout
__device__ __align__(16) float g_d0[NE];   // L_LR - 3u
__device__ __align__(16) float g_d1[NE];   // L_RL
__device__ __align__(16) float g_d2[NE];   // L_TD
__device__ __align__(16) float g_d3[NE];   // L_BU

// ---------------------------------------------------------------------------
// Transpose (B,D,H,W) -> (B,HW,D)
__global__ void __launch_bounds__(256)
transpose_in(const float* __restrict__ u) {
    __shared__ float tile[DL][TP + 1];
    const int blk = blockIdx.x;                 // NP/TP = 8192 blocks
    const int b   = blk / (HW / TP);
    const int tp  = blk % (HW / TP);
    const size_t p0 = (size_t)tp * TP;
    const float* ub = u + (size_t)b * DL * HW;
    for (int i = threadIdx.x; i < DL * TP; i += blockDim.x) {
        int l = i / TP, pp = i % TP;            // coalesced 512B row reads
        tile[l][pp] = ub[(size_t)l * HW + p0 + pp];
    }
    __syncthreads();
    float* ob = g_ut + ((size_t)b * HW + p0) * DL;
    for (int i = threadIdx.x; i < DL * TP; i += blockDim.x) {
        int pp = i / DL, l = i % DL;            // fully contiguous tile write
        ob[i] = tile[l][pp];
    }
}

// ---------------------------------------------------------------------------
// One DP step: min_k( shfl(L,k) + w * Vc[k] ), 3 parallel min chains.
__device__ __forceinline__ float mp_min(float L, float wval, const float (&Vc)[DL]) {
    const unsigned FM = 0xffffffffu;
    float m0 = fmaf(wval, Vc[0], __shfl_sync(FM, L, 0));
    float m1 = fmaf(wval, Vc[1], __shfl_sync(FM, L, 1));
    float m2 = fmaf(wval, Vc[2], __shfl_sync(FM, L, 2));
#pragma unroll
    for (int k = 3; k < DL; k += 3) {
        m0 = fminf(m0, fmaf(wval, Vc[k    ], __shfl_sync(FM, L, k    )));
        m1 = fminf(m1, fmaf(wval, Vc[k + 1], __shfl_sync(FM, L, k + 1)));
        m2 = fminf(m2, fmaf(wval, Vc[k + 2], __shfl_sync(FM, L, k + 2)));
    }
    return fminf(m0, fminf(m1, m2));
}

template<bool SUB3U>
__device__ __forceinline__ void sweep(const float* __restrict__ ub,   // (p,l) base for batch
                                      const float* __restrict__ wb,   // (p) base for batch,dir
                                      float* __restrict__ ob,         // (p,l) base for batch
                                      int pstart, int dp,
                                      const float (&Vc)[DL], int l, bool active) {
    const float* up = ub + (size_t)pstart * DL + l;
    const float* wp = wb + pstart;
    float*       op = ob + (size_t)pstart * DL + l;
    const int estride = dp * DL;

    float u = __ldg(up);
    float L = u;
    if (active) *op = SUB3U ? (L - 3.0f * u) : L;
#pragma unroll 2
    for (int t = 1; t < SS; t++) {
        up += estride; wp += dp; op += estride;
        float un = __ldg(up);
        float wn = __ldg(wp);
        L = un + mp_min(L, wn, Vc);
        if (active) *op = SUB3U ? (L - 3.0f * un) : L;
    }
}

// One kernel, all 4 directions: 8192 warps, each owns one (dir, b, line) chain.
__global__ void __launch_bounds__(256)
sweep_all(const float* __restrict__ ew, const float* __restrict__ lc) {
    const int gw   = (blockIdx.x * blockDim.x + threadIdx.x) >> 5;
    const int lane = threadIdx.x & 31;
    const int dir  = gw >> 11;
    const int r    = gw & 2047;
    const int b    = r >> 9;
    const int line = r & 511;
    const int l    = (lane < DL) ? lane : 0;
    const bool active = (lane < DL);

    float Vc[DL];
#pragma unroll
    for (int k = 0; k < DL; k++) Vc[k] = __ldg(lc + k * DL + l);

    const float* ub = g_ut + (size_t)b * HW * DL;
    const float* wb = ew + (size_t)(b * 4 + dir) * HW;

    if (dir == 0)       sweep<true >(ub, wb, g_d0 + (size_t)b * HW * DL,
                                     line * SS,            +1,  Vc, l, active);
    else if (dir == 1)  sweep<false>(ub, wb, g_d1 + (size_t)b * HW * DL,
                                     line * SS + SS - 1,   -1,  Vc, l, active);
    else if (dir == 2)  sweep<false>(ub, wb, g_d2 + (size_t)b * HW * DL,
                                     line,                 +SS, Vc, l, active);
    else                sweep<false>(ub, wb, g_d3 + (size_t)b * HW * DL,
                                     (SS - 1) * SS + line, -SS, Vc, l, active);
}

// ---------------------------------------------------------------------------
// out[b][l][p] = d0+d1+d2+d3 at (b,p,l)  (d0 already carries the -3u term)
__global__ void __launch_bounds__(256)
combine(float* __restrict__ out) {
    __shared__ float tile[DL][TP + 1];
    const int blk = blockIdx.x;
    const int b   = blk / (HW / TP);
    const int tp  = blk % (HW / TP);
    const size_t p0 = (size_t)tp * TP;
    const size_t base = ((size_t)b * HW + p0) * DL;
    for (int i = threadIdx.x; i < DL * TP; i += blockDim.x) {
        float v = g_d0[base + i] + g_d1[base + i] + g_d2[base + i] + g_d3[base + i];
        int pp = i / DL, l = i % DL;
        tile[l][pp] = v;
    }
    __syncthreads();
    float* ob = out + (size_t)b * DL * HW;
    for (int i = threadIdx.x; i < DL * TP; i += blockDim.x) {
        int l = i / TP, pp = i % TP;            // coalesced 512B row writes
        ob[(size_t)l * HW + p0 + pp] = tile[l][pp];
    }
}

// ---------------------------------------------------------------------------
extern "C" void kernel_launch(void* const* d_in, const int* in_sizes, int n_in,
                              void* d_out, int out_size) {
    const float* unary = (const float*)d_in[0];   // (4,1,21,512,512)
    const float* ew    = (const float*)d_in[1];   // (4,4,512,512)
    const float* lc    = (const float*)d_in[2];   // (21,21)
    float* out = (float*)d_out;                   // (4,1,21,512,512)

    transpose_in<<<NP / TP, 256>>>(unary);
    sweep_all<<<1024, 256>>>(ew, lc);
    combine<<<NP / TP, 256>>>(out);
}

// round 4
// speedup vs baseline: 1.6544x; 1.2064x over previous
#include <cuda_runtime.h>
#include <cstdint>

#define DL 21
#define SS 512
#define HW (SS*SS)
#define NB 4
#define NE (NB*DL*HW)   // 22,020,096 (~84 MB fp32)

// Spatially transposed unary (b,l,x,y) and edge weights for dirs 0/1
__device__ __align__(16) float g_uT[NE];
__device__ __align__(16) float g_ewT[NB*2*HW];
// Directional results: o0/o1 stored in transposed space (step axis = x)
__device__ __align__(16) float g_o0[NE];
__device__ __align__(16) float g_o1[NE];
__device__ __align__(16) float g_o2[NE];   // carries -3u
__device__ __align__(16) float g_o3[NE];

// ---------------------------------------------------------------------------
// 32x32 tile transpose of one 512x512 plane: dst[x][y] = src[y][x]
__device__ __forceinline__ void tr_tile(const float* __restrict__ sp,
                                        float* __restrict__ dp, int tt) {
    __shared__ float tile[32][33];
    const int ty0 = (tt >> 4) << 5;
    const int tx0 = (tt & 15) << 5;
    const int lx = threadIdx.x & 31, ly = threadIdx.x >> 5;   // 32x8
#pragma unroll
    for (int j = 0; j < 4; j++) {
        int y = ty0 + ly + 8*j;
        tile[ly + 8*j][lx] = sp[(size_t)y * SS + tx0 + lx];
    }
    __syncthreads();
#pragma unroll
    for (int j = 0; j < 4; j++) {
        int x = tx0 + ly + 8*j;
        dp[(size_t)x * SS + ty0 + lx] = tile[lx][ly + 8*j];
    }
}

__global__ void __launch_bounds__(256)
transpose_u(const float* __restrict__ u) {
    const int plane = blockIdx.x >> 8;        // b*21+l (84 planes)
    tr_tile(u + (size_t)plane * HW, g_uT + (size_t)plane * HW, blockIdx.x & 255);
}

__global__ void __launch_bounds__(256)
transpose_ew(const float* __restrict__ ew) {
    const int plane = blockIdx.x >> 8;        // b*2+d (8 planes, d=0,1)
    const int b = plane >> 1, d = plane & 1;
    tr_tile(ew + ((size_t)b*4 + d) * HW, g_ewT + (size_t)plane * HW, blockIdx.x & 255);
}

// ---------------------------------------------------------------------------
// Sweep: block = 32 columns x 11 label-pairs (352 threads), one dir/b/colblock.
// All four directions are column-parallel scans (dirs 0/1 run on the
// transposed image). L broadcast via double-buffered smem, 1 sync/step.
__global__ void __launch_bounds__(352, 2)
sweep(const float* __restrict__ u, const float* __restrict__ ew,
      const float* __restrict__ lc) {
    __shared__ float Lb[2][32][DL];
    const int bx   = blockIdx.x;
    const int dir  = bx >> 6;
    const int b    = (bx >> 4) & 3;
    const int col0 = (bx & 15) << 5;
    const int c    = threadIdx.x & 31;
    const int lg   = threadIdx.x >> 5;        // 0..10
    const int l0   = 2 * lg;
    const bool has2 = (lg < 10);
    const int l1   = has2 ? l0 + 1 : l0;

    float V0[DL], V1[DL];
#pragma unroll
    for (int k = 0; k < DL; k++) {
        V0[k] = __ldg(lc + k * DL + l0);
        V1[k] = __ldg(lc + k * DL + l1);
    }

    const float* src; const float* wsrc; float* dst;
    int start, strd; float s3 = 0.0f;
    if (dir == 0)      { src = g_uT; wsrc = g_ewT + (size_t)(b*2+0)*HW; dst = g_o0; start = 0;           strd =  SS; }
    else if (dir == 1) { src = g_uT; wsrc = g_ewT + (size_t)(b*2+1)*HW; dst = g_o1; start = (SS-1)*SS;   strd = -SS; }
    else if (dir == 2) { src = u;    wsrc = ew   + (size_t)(b*4+2)*HW;  dst = g_o2; start = 0;           strd =  SS; s3 = 3.0f; }
    else               { src = u;    wsrc = ew   + (size_t)(b*4+3)*HW;  dst = g_o3; start = (SS-1)*SS;   strd = -SS; }

    const size_t p0 = (size_t)(b*DL + l0) * HW + start + col0 + c;
    const size_t p1 = (size_t)(b*DL + l1) * HW + start + col0 + c;
    const float* pu0 = src + p0;
    const float* pu1 = src + p1;
    const float* pw  = wsrc + start + col0 + c;
    float* po0 = dst + p0;
    float* po1 = dst + p1;

    // border: L = u
    float u0 = __ldg(pu0), u1 = __ldg(pu1);
    float L0 = u0, L1 = u1;
    *po0 = fmaf(-s3, u0, L0);
    if (has2) *po1 = fmaf(-s3, u1, L1);
    Lb[0][c][l0] = L0;
    Lb[0][c][l1] = L1;
    __syncthreads();

#pragma unroll 1
    for (int t = 1; t < SS; t++) {
        pu0 += strd; pu1 += strd; pw += strd; po0 += strd; po1 += strd;
        const float un0 = __ldg(pu0);
        const float un1 = __ldg(pu1);
        const float wv  = __ldg(pw);
        const float* Lo = Lb[(t - 1) & 1][c];

        float a0, a1, a2, e0, e1, e2;
        {
            float x0 = Lo[0], x1 = Lo[1], x2 = Lo[2];
            a0 = fmaf(wv, V0[0], x0); a1 = fmaf(wv, V0[1], x1); a2 = fmaf(wv, V0[2], x2);
            e0 = fmaf(wv, V1[0], x0); e1 = fmaf(wv, V1[1], x1); e2 = fmaf(wv, V1[2], x2);
        }
#pragma unroll
        for (int k = 3; k < DL; k += 3) {
            float x0 = Lo[k], x1 = Lo[k + 1], x2 = Lo[k + 2];
            a0 = fminf(a0, fmaf(wv, V0[k    ], x0));
            a1 = fminf(a1, fmaf(wv, V0[k + 1], x1));
            a2 = fminf(a2, fmaf(wv, V0[k + 2], x2));
            e0 = fminf(e0, fmaf(wv, V1[k    ], x0));
            e1 = fminf(e1, fmaf(wv, V1[k + 1], x1));
            e2 = fminf(e2, fmaf(wv, V1[k + 2], x2));
        }
        L0 = un0 + fminf(a0, fminf(a1, a2));
        L1 = un1 + fminf(e0, fminf(e1, e2));
        *po0 = fmaf(-s3, un0, L0);
        if (has2) *po1 = fmaf(-s3, un1, L1);
        Lb[t & 1][c][l0] = L0;
        Lb[t & 1][c][l1] = L1;
        __syncthreads();
    }
}

// ---------------------------------------------------------------------------
// out(b,l,y,x) = o2(y,x) + o3(y,x) + o0(x,y) + o1(x,y)   [o2 carries -3u]
__global__ void __launch_bounds__(256)
combine(float* __restrict__ out) {
    __shared__ float t0[32][33], t1[32][33];
    const int plane = blockIdx.x >> 8;        // b*21+l
    const int tt = blockIdx.x & 255;
    const int y0 = (tt >> 4) << 5;
    const int x0 = (tt & 15) << 5;
    const size_t pb = (size_t)plane * HW;
    const int lx = threadIdx.x & 31, ly = threadIdx.x >> 5;
#pragma unroll
    for (int j = 0; j < 4; j++) {
        int x = x0 + ly + 8*j;
        size_t idx = pb + (size_t)x * SS + y0 + lx;
        t0[lx][ly + 8*j] = g_o0[idx];
        t1[lx][ly + 8*j] = g_o1[idx];
    }
    __syncthreads();
#pragma unroll
    for (int j = 0; j < 4; j++) {
        int y = y0 + ly + 8*j;
        size_t idx = pb + (size_t)y * SS + x0 + lx;
        out[idx] = g_o2[idx] + g_o3[idx] + t0[ly + 8*j][lx] + t1[ly + 8*j][lx];
    }
}

// ---------------------------------------------------------------------------
extern "C" void kernel_launch(void* const* d_in, const int* in_sizes, int n_in,
                              void* d_out, int out_size) {
    const float* unary = (const float*)d_in[0];   // (4,1,21,512,512)
    const float* ew    = (const float*)d_in[1];   // (4,4,512,512)
    const float* lc    = (const float*)d_in[2];   // (21,21)
    float* out = (float*)d_out;                   // (4,1,21,512,512)

    transpose_u <<<NB * DL * 256, 256>>>(unary);
    transpose_ew<<<NB * 2 * 256, 256>>>(ew);
    sweep<<<256, 352>>>(unary, ew, lc);
    combine<<<NB * DL * 256, 256>>>(out);
}

// round 5
// speedup vs baseline: 1.7944x; 1.0846x over previous
#include <cuda_runtime.h>
#include <cstdint>
#include <cfloat>

#define DL 21
#define SS 512
#define HW (SS*SS)
#define NB 4
#define NE (NB*DL*HW)   // 22,020,096 (~84 MB fp32)

// Spatially transposed unary (b,l,x,y) and edge weights for dirs 0/1
__device__ __align__(16) float g_uT[NE];
__device__ __align__(16) float g_ewT[NB*2*HW];
// Directional results: o0/o1 in transposed space; o2 carries -3u
__device__ __align__(16) float g_o0[NE];
__device__ __align__(16) float g_o1[NE];
__device__ __align__(16) float g_o2[NE];
__device__ __align__(16) float g_o3[NE];

// ---------------------------------------------------------------------------
// Packed f32x2 helpers (Blackwell FFMA2)
__device__ __forceinline__ unsigned long long f2u(float x, float y) {
    unsigned long long r;
    asm("mov.b64 %0, {%1, %2};" : "=l"(r) : "f"(x), "f"(y));
    return r;
}
__device__ __forceinline__ float2 u2f(unsigned long long v) {
    float2 r;
    asm("mov.b64 {%0, %1}, %2;" : "=f"(r.x), "=f"(r.y) : "l"(v));
    return r;
}
__device__ __forceinline__ unsigned long long ffma2u(unsigned long long a,
                                                     unsigned long long b,
                                                     unsigned long long c) {
    unsigned long long d;
    asm("fma.rn.f32x2 %0, %1, %2, %3;" : "=l"(d) : "l"(a), "l"(b), "l"(c));
    return d;
}

// ---------------------------------------------------------------------------
// 32x32 tile transpose using float4, conflict-free padded tile
__device__ __forceinline__ void tr_tile4(const float* __restrict__ sp,
                                         float* __restrict__ dp, int tt, int tid) {
    __shared__ float tile[32][33];
    const int ty0 = (tt >> 4) << 5;
    const int tx0 = (tt & 15) << 5;
    const int r  = tid >> 3;
    const int q4 = (tid & 7) << 2;
    float4 v = *reinterpret_cast<const float4*>(sp + (size_t)(ty0 + r) * SS + tx0 + q4);
    tile[r][q4 + 0] = v.x; tile[r][q4 + 1] = v.y;
    tile[r][q4 + 2] = v.z; tile[r][q4 + 3] = v.w;
    __syncthreads();
    float4 o = make_float4(tile[q4 + 0][r], tile[q4 + 1][r],
                           tile[q4 + 2][r], tile[q4 + 3][r]);
    *reinterpret_cast<float4*>(dp + (size_t)(tx0 + r) * SS + ty0 + q4) = o;
}

// planes 0..83: unary; 84..91: edge weights dirs 0/1
__global__ void __launch_bounds__(256)
transpose_all(const float* __restrict__ u, const float* __restrict__ ew) {
    const int plane = blockIdx.x >> 8;
    const int tt = blockIdx.x & 255;
    if (plane < NB * DL) {
        tr_tile4(u + (size_t)plane * HW, g_uT + (size_t)plane * HW, tt, threadIdx.x);
    } else {
        const int p = plane - NB * DL;          // 0..7
        const int b = p >> 1, d = p & 1;
        tr_tile4(ew + (size_t)(b * 4 + d) * HW, g_ewT + (size_t)p * HW, tt, threadIdx.x);
    }
}

// ---------------------------------------------------------------------------
// Sweep: block = 32 columns x 11 label-pair warps, smem L-exchange,
// software-prefetched global loads, packed FFMA2 inner loop.
template<int DIR>
__device__ __forceinline__ void run_sweep(const float* __restrict__ u,
                                          const float* __restrict__ ew,
                                          int b, int col0, int c, int lg,
                                          bool has2, int base0, int base1,
                                          const unsigned long long (&Vp0)[11],
                                          const unsigned long long (&Vp1)[11],
                                          unsigned long long (*Lb)[32][11]) {
    const float* src  = (DIR < 2) ? g_uT : u;
    const float* wsrc = (DIR < 2) ? (g_ewT + (size_t)(b * 2 + DIR) * HW)
                                  : (ew   + (size_t)(b * 4 + DIR) * HW);
    float* dst = (DIR == 0) ? g_o0 : (DIR == 1) ? g_o1 : (DIR == 2) ? g_o2 : g_o3;
    constexpr int STRD = (DIR == 0 || DIR == 2) ? SS : -SS;
    const int start = (STRD > 0) ? 0 : (SS - 1) * SS;
    const int wb = col0 + c;

    float L0, L1;
    int offL = start;
    // t = 0 (border: L = u)
    {
        float cu0 = __ldg(src + base0 + offL);
        float cu1 = __ldg(src + base1 + offL);
        L0 = cu0; L1 = cu1;
        dst[base0 + offL] = (DIR == 2) ? fmaf(-3.0f, cu0, L0) : L0;
        if (has2) dst[base1 + offL] = (DIR == 2) ? fmaf(-3.0f, cu1, L1) : L1;
        Lb[0][c][lg] = f2u(L0, has2 ? L1 : FLT_MAX);
    }
    // prefetch t = 1, t = 2
    offL += STRD;
    float au0 = __ldg(src + base0 + offL);
    float au1 = __ldg(src + base1 + offL);
    float aw  = __ldg(wsrc + wb + offL);
    offL += STRD;
    float bu0 = __ldg(src + base0 + offL);
    float bu1 = __ldg(src + base1 + offL);
    float bw  = __ldg(wsrc + wb + offL);
    __syncthreads();

    auto stepf = [&](int wp, float u0v, float u1v, float wv, int offS) {
        const unsigned long long* Lo = Lb[wp ^ 1][c];
        const unsigned long long w2 = f2u(wv, wv);
        unsigned long long xu = Lo[0];
        float2 cA = u2f(ffma2u(w2, Vp0[0], xu));
        float2 cE = u2f(ffma2u(w2, Vp1[0], xu));
        float a0 = cA.x, a1 = cA.y, e0 = cE.x, e1 = cE.y;
#pragma unroll
        for (int kk = 1; kk < 11; kk++) {
            xu = Lo[kk];
            cA = u2f(ffma2u(w2, Vp0[kk], xu));
            cE = u2f(ffma2u(w2, Vp1[kk], xu));
            a0 = fminf(a0, cA.x); a1 = fminf(a1, cA.y);
            e0 = fminf(e0, cE.x); e1 = fminf(e1, cE.y);
        }
        L0 = u0v + fminf(a0, a1);
        L1 = u1v + fminf(e0, e1);
        dst[base0 + offS] = (DIR == 2) ? fmaf(-3.0f, u0v, L0) : L0;
        if (has2) dst[base1 + offS] = (DIR == 2) ? fmaf(-3.0f, u1v, L1) : L1;
        Lb[wp][c][lg] = f2u(L0, has2 ? L1 : FLT_MAX);
    };

    int offS = start;
#pragma unroll 1
    for (int t = 1; t <= SS - 3; t++) {
        offS += STRD;
        stepf(t & 1, au0, au1, aw, offS);
        au0 = bu0; au1 = bu1; aw = bw;
        offL += STRD;
        bu0 = __ldg(src + base0 + offL);
        bu1 = __ldg(src + base1 + offL);
        bw  = __ldg(wsrc + wb + offL);
        __syncthreads();
    }
    // t = SS-2
    offS += STRD;
    stepf((SS - 2) & 1, au0, au1, aw, offS);
    au0 = bu0; au1 = bu1; aw = bw;
    __syncthreads();
    // t = SS-1
    offS += STRD;
    stepf((SS - 1) & 1, au0, au1, aw, offS);
}

__global__ void __launch_bounds__(352, 2)
sweep(const float* __restrict__ u, const float* __restrict__ ew,
      const float* __restrict__ lc) {
    __shared__ unsigned long long Lb[2][32][11];
    const int bx   = blockIdx.x;
    const int dir  = bx >> 6;
    const int b    = (bx >> 4) & 3;
    const int col0 = (bx & 15) << 5;
    const int c    = threadIdx.x & 31;
    const int lg   = threadIdx.x >> 5;
    const int l0   = 2 * lg;
    const bool has2 = (lg < 10);
    const int l1   = has2 ? l0 + 1 : l0;

    // V pairs packed along k (source label): Vp[kk] = {V[2kk][l], V[2kk+1][l]}
    unsigned long long Vp0[11], Vp1[11];
#pragma unroll
    for (int kk = 0; kk < 11; kk++) {
        const int ka = 2 * kk, kb = 2 * kk + 1;
        float va0 = __ldg(lc + ka * DL + l0);
        float vb0 = (kb < DL) ? __ldg(lc + kb * DL + l0) : 0.0f;
        float va1 = __ldg(lc + ka * DL + l1);
        float vb1 = (kb < DL) ? __ldg(lc + kb * DL + l1) : 0.0f;
        Vp0[kk] = f2u(va0, vb0);
        Vp1[kk] = f2u(va1, vb1);
    }

    const int base0 = (b * DL + l0) * HW + col0 + c;
    const int base1 = (b * DL + l1) * HW + col0 + c;

    if (dir == 0)      run_sweep<0>(u, ew, b, col0, c, lg, has2, base0, base1, Vp0, Vp1, Lb);
    else if (dir == 1) run_sweep<1>(u, ew, b, col0, c, lg, has2, base0, base1, Vp0, Vp1, Lb);
    else if (dir == 2) run_sweep<2>(u, ew, b, col0, c, lg, has2, base0, base1, Vp0, Vp1, Lb);
    else               run_sweep<3>(u, ew, b, col0, c, lg, has2, base0, base1, Vp0, Vp1, Lb);
}

// ---------------------------------------------------------------------------
// out(b,l,y,x) = o2(y,x) + o3(y,x) + o0(x,y) + o1(x,y)   [o2 carries -3u]
__global__ void __launch_bounds__(256)
combine(float* __restrict__ out) {
    __shared__ float t0[32][33], t1[32][33];
    const int plane = blockIdx.x >> 8;       // b*21+l
    const int tt = blockIdx.x & 255;
    const int y0 = (tt >> 4) << 5;
    const int x0 = (tt & 15) << 5;
    const size_t pb = (size_t)plane * HW;
    const int r  = threadIdx.x >> 3;
    const int q4 = (threadIdx.x & 7) << 2;
    {   // load transposed planes: rows along x, vectorized along y
        size_t idx = pb + (size_t)(x0 + r) * SS + y0 + q4;
        float4 a = *reinterpret_cast<const float4*>(g_o0 + idx);
        float4 bq = *reinterpret_cast<const float4*>(g_o1 + idx);
        t0[r][q4 + 0] = a.x;  t0[r][q4 + 1] = a.y;
        t0[r][q4 + 2] = a.z;  t0[r][q4 + 3] = a.w;
        t1[r][q4 + 0] = bq.x; t1[r][q4 + 1] = bq.y;
        t1[r][q4 + 2] = bq.z; t1[r][q4 + 3] = bq.w;
    }
    __syncthreads();
    {   // stream o2/o3 + add transposed tiles, vectorized along x
        size_t idx = pb + (size_t)(y0 + r) * SS + x0 + q4;
        float4 r2 = *reinterpret_cast<const float4*>(g_o2 + idx);
        float4 r3 = *reinterpret_cast<const float4*>(g_o3 + idx);
        float4 o;
        o.x = r2.x + r3.x + t0[q4 + 0][r] + t1[q4 + 0][r];
        o.y = r2.y + r3.y + t0[q4 + 1][r] + t1[q4 + 1][r];
        o.z = r2.z + r3.z + t0[q4 + 2][r] + t1[q4 + 2][r];
        o.w = r2.w + r3.w + t0[q4 + 3][r] + t1[q4 + 3][r];
        *reinterpret_cast<float4*>(out + idx) = o;
    }
}

// ---------------------------------------------------------------------------
extern "C" void kernel_launch(void* const* d_in, const int* in_sizes, int n_in,
                              void* d_out, int out_size) {
    const float* unary = (const float*)d_in[0];   // (4,1,21,512,512)
    const float* ew    = (const float*)d_in[1];   // (4,4,512,512)
    const float* lc    = (const float*)d_in[2];   // (21,21)
    float* out = (float*)d_out;                   // (4,1,21,512,512)

    transpose_all<<<(NB * DL + NB * 2) * 256, 256>>>(unary, ew);
    sweep<<<256, 352>>>(unary, ew, lc);
    combine<<<NB * DL * 256, 256>>>(out);
}